// round 14
// baseline (speedup 1.0000x reference)
#include <cuda_runtime.h>
#include <math_constants.h>
#include <cstdint>

// Problem constants
#define NB      32
#define DIM     64
#define HW      4096            // 64*64
#define N_ROWS  (NB * HW)       // 131072
#define N_CODES 1024
#define N_ELEMS (N_ROWS * DIM)  // 8388608

#define N_TILES 16              // code tiles of 64
#define N_BLOCKS (N_ROWS / 128) // 1024

// Dynamic smem layout for fused kernel
#define SM_Z    0               // ulonglong [32][128] = 32768 B (z pairs [k2][row])
#define SM_E    32768           // ulonglong [32][64]  = 16384 B (code pairs [k2][c])
#define SM_S2   49152           // float [1024]        = 4096 B
#define SM_BIDX 53248           // int [128]           = 512 B
#define SM_RED  53760           // double [8]          = 64 B
#define SMEM_TOTAL 53824

// Device scratch (no allocations allowed)
__device__ double             g_partials[N_BLOCKS];
__device__ float              g_s2[N_CODES];
__device__ unsigned long long g_cbt[N_CODES * 32];   // [tile][k2][c] packed pairs

// ---- packed fp32x2 helpers (sm_100+) ---------------------------------------
__device__ __forceinline__ void fma2(unsigned long long& d,
                                     unsigned long long a,
                                     unsigned long long b) {
    asm("fma.rn.f32x2 %0, %1, %2, %0;" : "+l"(d) : "l"(a), "l"(b));
}
__device__ __forceinline__ unsigned long long pack2(float lo, float hi) {
    unsigned long long r;
    asm("mov.b64 %0, {%1, %2};" : "=l"(r) : "f"(lo), "f"(hi));
    return r;
}
__device__ __forceinline__ void unpack2(unsigned long long p, float& lo, float& hi) {
    asm("mov.b64 {%0, %1}, %2;" : "=f"(lo), "=f"(hi) : "l"(p));
}

// ---------------------------------------------------------------------------
// Kernel 0 (prep): exact per-code s2 (sequential fp32 chain, proven) and the
// pair-transposed codebook g_cbt[tile*2048 + k2*64 + cloc] = (e_{2k2}, e_{2k2+1}).
// ---------------------------------------------------------------------------
__global__ void __launch_bounds__(256)
vq_prep_kernel(const float* __restrict__ cb)
{
    const int c = blockIdx.x * 256 + threadIdx.x;
    if (c >= N_CODES) return;
    const float* ep = cb + (size_t)c * DIM;
    const int tbase = (c >> 6) * 2048 + (c & 63);
    float acc = 0.0f;
    #pragma unroll
    for (int k2 = 0; k2 < 32; k2++) {
        float e0 = ep[2 * k2];
        float e1 = ep[2 * k2 + 1];
        acc = __fadd_rn(acc, __fmul_rn(e0, e0));
        acc = __fadd_rn(acc, __fmul_rn(e1, e1));
        g_cbt[tbase + k2 * 64] = pack2(e0, e1);
    }
    g_s2[c] = acc;
}

// ---------------------------------------------------------------------------
// Kernel 1 (fused): register-tiled argmin (R=4 rows x C=8 codes, R11 tile,
// 6x rel_err=0.0 chain) + in-place apply epilogue (gather, straight-through
// out, fp64 loss partial). 1024 blocks x 256 threads; block = 128 rows.
// Thread (ry=tid>>3, cx=tid&7) owns rows ry*4..+3 and codes cx*8..cx*8+7
// (contiguous -> er fetched as 4x LDS.128; zr as 2x LDS.128).
// ---------------------------------------------------------------------------
__global__ void __launch_bounds__(256, 2)
vq_fused_kernel(const float* __restrict__ z, const float* __restrict__ cb,
                float* __restrict__ out)
{
    extern __shared__ char smem[];
    unsigned long long* s_z  = (unsigned long long*)(smem + SM_Z);
    unsigned long long* s_e  = (unsigned long long*)(smem + SM_E);
    float*              s_s2 = (float*)(smem + SM_S2);
    float*              s_zf = (float*)(smem + SM_Z);
    int*                s_bi = (int*)(smem + SM_BIDX);
    double*             s_rd = (double*)(smem + SM_RED);

    const int tid = threadIdx.x;
    const int ry  = tid >> 3;     // 0..31  -> rows ry*4..ry*4+3
    const int cx  = tid & 7;      // 0..7   -> codes cx*8..cx*8+7 per tile
    const int r0  = blockIdx.x * 128;
    const int b   = r0 >> 12;
    const int hw0 = r0 & 4095;

    // stage s2 table
    #pragma unroll
    for (int i = 0; i < 4; i++) s_s2[tid + i * 256] = g_s2[tid + i * 256];

    // stage z tile as pairs [k2][row] (coalesced gmem float4 reads)
    const float* zb = z + (size_t)b * (DIM * HW) + hw0;
    #pragma unroll
    for (int i = 0; i < 8; i++) {
        int idx = tid + i * 256;         // 0..2047
        int k = idx >> 5;                // dim
        int g = idx & 31;                // group of 4 rows
        float4 v = *(const float4*)(zb + (size_t)k * HW + g * 4);
        int base = ((k >> 1) * 128 + g * 4) * 2 + (k & 1);
        s_zf[base]     = v.x;
        s_zf[base + 2] = v.y;
        s_zf[base + 4] = v.z;
        s_zf[base + 6] = v.w;
    }
    __syncthreads();

    // exact s1 per owned row: fp64 sum of fp32 squares, ascending k (proven)
    float s1[4];
    #pragma unroll
    for (int i = 0; i < 4; i++) {
        const int row = ry * 4 + i;
        double acc = 0.0;
        #pragma unroll
        for (int k2 = 0; k2 < 32; k2++) {
            float lo, hi; unpack2(s_z[k2 * 128 + row], lo, hi);
            acc += (double)__fmul_rn(lo, lo);
            acc += (double)__fmul_rn(hi, hi);
        }
        s1[i] = (float)acc;
    }

    unsigned long long acc[4][8];
    #pragma unroll
    for (int i = 0; i < 4; i++)
        #pragma unroll
        for (int j = 0; j < 8; j++) acc[i][j] = 0ull;

    float best[4];
    int   bidx[4];
    #pragma unroll
    for (int i = 0; i < 4; i++) { best[i] = CUDART_INF_F; bidx[i] = 0; }

    for (int tn = 0; tn < N_TILES; tn++) {
        // stage code tile [k2][c] (contiguous, coalesced)
        const unsigned long long* src = g_cbt + tn * 2048;
        #pragma unroll
        for (int i = 0; i < 8; i++)
            s_e[tid + i * 256] = src[tid + i * 256];
        __syncthreads();

        #pragma unroll 4
        for (int k2 = 0; k2 < 32; k2++) {
            unsigned long long zr[4], er[8];
            #pragma unroll
            for (int m = 0; m < 2; m++) {
                ulonglong2 v = *(const ulonglong2*)&s_z[k2 * 128 + ry * 4 + 2 * m];
                zr[2 * m] = v.x; zr[2 * m + 1] = v.y;
            }
            #pragma unroll
            for (int m = 0; m < 4; m++) {
                ulonglong2 v = *(const ulonglong2*)&s_e[k2 * 64 + cx * 8 + 2 * m];
                er[2 * m] = v.x; er[2 * m + 1] = v.y;
            }
            #pragma unroll
            for (int i = 0; i < 4; i++)
                #pragma unroll
                for (int j = 0; j < 8; j++)
                    fma2(acc[i][j], zr[i], er[j]);
        }

        // epilogue: fold + compare (codes ascending in j per thread)
        const int c0 = tn * 64 + cx * 8;
        float4 s2a = *(const float4*)&s_s2[c0];
        float4 s2b = *(const float4*)&s_s2[c0 + 4];
        float s2v[8] = {s2a.x, s2a.y, s2a.z, s2a.w, s2b.x, s2b.y, s2b.z, s2b.w};
        #pragma unroll
        for (int i = 0; i < 4; i++) {
            #pragma unroll
            for (int j = 0; j < 8; j++) {
                float lo, hi; unpack2(acc[i][j], lo, hi);
                float cross = __fadd_rn(lo, hi);
                float tt    = __fadd_rn(s1[i], s2v[j]);
                float score = __fmaf_rn(-2.0f, cross, tt);
                if (score < best[i]) { best[i] = score; bidx[i] = c0 + j; }
                acc[i][j] = 0ull;
            }
        }
        __syncthreads();   // reads done before next tile overwrites s_e
    }

    // merge across the 8 code lanes (same rows): min score, tie -> min index
    #pragma unroll
    for (int off = 1; off <= 4; off <<= 1) {
        #pragma unroll
        for (int i = 0; i < 4; i++) {
            float os = __shfl_down_sync(0xffffffffu, best[i], off);
            int   oi = __shfl_down_sync(0xffffffffu, bidx[i], off);
            if (os < best[i] || (os == best[i] && oi < bidx[i])) {
                best[i] = os; bidx[i] = oi;
            }
        }
    }
    if (cx == 0) {
        #pragma unroll
        for (int i = 0; i < 4; i++)
            s_bi[ry * 4 + i] = bidx[i];
    }
    __syncthreads();

    // ---- fused apply: out = RN(z + RN(q - z)); fp64 loss partial ----------
    // element idx = tid + it*256 over 8192 = 64 ch x 128 rows;
    // c = idx>>7 (0..63), i = idx&127 (0..127)
    float* ob = out + (size_t)b * (DIM * HW) + hw0;
    double dd = 0.0;
    #pragma unroll
    for (int it = 0; it < 32; it++) {
        const int idx = tid + it * 256;
        const int c   = idx >> 7;
        const int i   = idx & 127;
        const float zv = s_zf[((c >> 1) * 128 + i) * 2 + (c & 1)];
        const float qv = cb[s_bi[i] * DIM + c];
        const float d  = __fadd_rn(qv, -zv);
        ob[(size_t)c * HW + i] = __fadd_rn(zv, d);
        dd += (double)__fmul_rn(d, d);
    }

    // deterministic block reduction of dd
    const int lane = tid & 31;
    const int wid  = tid >> 5;
    #pragma unroll
    for (int off = 16; off > 0; off >>= 1)
        dd += __shfl_down_sync(0xffffffffu, dd, off);
    if (lane == 0) s_rd[wid] = dd;
    __syncthreads();
    if (tid == 0) {
        double v = 0.0;
        #pragma unroll
        for (int i = 0; i < 8; i++) v += s_rd[i];
        g_partials[blockIdx.x] = v;
    }
}

// ---------------------------------------------------------------------------
// Kernel 2: deterministic final reduction + loss
// vq_loss = m + 0.25*m,  m = mean((z_q - z)^2)
// ---------------------------------------------------------------------------
__global__ void __launch_bounds__(1024)
vq_loss_kernel(float* __restrict__ out, long long loss_pos)
{
    __shared__ double s_buf[N_BLOCKS];
    const int tid = threadIdx.x;
    s_buf[tid] = g_partials[tid];
    __syncthreads();
    #pragma unroll
    for (int s = N_BLOCKS / 2; s > 0; s >>= 1) {
        if (tid < s) s_buf[tid] += s_buf[tid + s];
        __syncthreads();
    }
    if (tid == 0) {
        float m = (float)(s_buf[0] * (1.0 / (double)N_ELEMS));
        float v = __fadd_rn(m, __fmul_rn(0.25f, m));
        out[loss_pos] = v;
    }
}

// ---------------------------------------------------------------------------
extern "C" void kernel_launch(void* const* d_in, const int* in_sizes, int n_in,
                              void* d_out, int out_size)
{
    const float* z  = (const float*)d_in[0];   // [32, 64, 64, 64] fp32
    const float* cb = (const float*)d_in[1];   // [1024, 64] fp32
    float* out = (float*)d_out;                // [8388608 z_q_st] + [1 loss]

    cudaFuncSetAttribute(vq_fused_kernel,
                         cudaFuncAttributeMaxDynamicSharedMemorySize, SMEM_TOTAL);

    vq_prep_kernel<<<4, 256>>>(cb);
    vq_fused_kernel<<<N_BLOCKS, 256, SMEM_TOTAL>>>(z, cb, out);

    long long loss_pos = (long long)out_size - 1;
    if (loss_pos < N_ELEMS) loss_pos = N_ELEMS;  // defensive; expect 8388609
    vq_loss_kernel<<<1, 1024>>>(out, loss_pos);
}

// round 15
// speedup vs baseline: 1.9586x; 1.9586x over previous
#include <cuda_runtime.h>
#include <math_constants.h>
#include <cstdint>

// Problem constants
#define NB      32
#define DIM     64
#define HW      4096            // 64*64
#define N_ROWS  (NB * HW)       // 131072
#define N_CODES 1024
#define N_ELEMS (N_ROWS * DIM)  // 8388608

#define N_TILES 16              // code tiles of 64
#define K2_BLOCKS  512
#define K2_THREADS 1024

// Dynamic smem layout for argmin kernel
#define SM_Z   0                // ulonglong [32][128] = 32768 B (z pairs [k2][row])
#define SM_E   32768            // ulonglong [2048]    = 16384 B (tile, interleaved)
#define SM_S2  49152            // float [1024]        = 4096 B
#define SMEM_TOTAL 53248

// Device scratch (no allocations allowed)
__device__ int                g_best_idx[N_ROWS];
__device__ double             g_partials[K2_BLOCKS];
__device__ float              g_s2[N_CODES];
// interleaved: [tile][k2][m][cx][half] ulonglong; per tile 32*4*8*2 = 2048
__device__ unsigned long long g_cbt[N_CODES * 32];

// ---- packed fp32x2 helpers (sm_100+) ---------------------------------------
__device__ __forceinline__ void fma2(unsigned long long& d,
                                     unsigned long long a,
                                     unsigned long long b) {
    asm("fma.rn.f32x2 %0, %1, %2, %0;" : "+l"(d) : "l"(a), "l"(b));
}
__device__ __forceinline__ unsigned long long pack2(float lo, float hi) {
    unsigned long long r;
    asm("mov.b64 %0, {%1, %2};" : "=l"(r) : "f"(lo), "f"(hi));
    return r;
}
__device__ __forceinline__ void unpack2(unsigned long long p, float& lo, float& hi) {
    asm("mov.b64 {%0, %1}, %2;" : "=f"(lo), "=f"(hi) : "l"(p));
}

// ---------------------------------------------------------------------------
// Kernel 0 (prep): exact per-code s2 (sequential fp32 chain, proven) and the
// interleaved pair-packed codebook:
//   g_cbt[ t*2048 + (k2*4 + m)*16 + cx*2 + half ] = pack2(e_c[2k2], e_c[2k2+1])
//   where c = t*64 + cx*8 + 2m + half.
// This makes the kernel's er fetch (ulonglong2 at byte k2*512+m*128+cx*16)
// conflict-free: for fixed m, the 8 cx addresses live in one 128-B row.
// ---------------------------------------------------------------------------
__global__ void __launch_bounds__(256)
vq_prep_kernel(const float* __restrict__ cb)
{
    const int c = blockIdx.x * 256 + threadIdx.x;
    if (c >= N_CODES) return;
    const float* ep = cb + (size_t)c * DIM;
    const int t    = c >> 6;
    const int cl   = c & 63;
    const int cx   = cl >> 3;
    const int m    = (cl & 7) >> 1;
    const int half = cl & 1;
    const int base = t * 2048 + m * 16 + cx * 2 + half;   // + k2*64
    float acc = 0.0f;
    #pragma unroll
    for (int k2 = 0; k2 < 32; k2++) {
        float e0 = ep[2 * k2];
        float e1 = ep[2 * k2 + 1];
        acc = __fadd_rn(acc, __fmul_rn(e0, e0));
        acc = __fadd_rn(acc, __fmul_rn(e1, e1));
        g_cbt[base + k2 * 64] = pack2(e0, e1);
    }
    g_s2[c] = acc;
}

// ---------------------------------------------------------------------------
// Kernel 1: register-tiled argmin (R=4 rows x C=8 codes). 1024 blocks x 256
// threads; block covers 128 rows x 1024 codes. Thread (ry=tid>>3, cx=tid&7)
// owns rows ry*4..+3 and codes cx*8..cx*8+7 per tile. Operands fetched as
// conflict-free LDS.128: zr 2x ulonglong2, er 4x ulonglong2 (interleaved
// layout). Score chain identical to the six passing rounds:
// score = fmaf(-2, cross, RN(s1+s2)); cross = RN(lo+hi); strict < ascending;
// lane merge (score, min-index).
// ---------------------------------------------------------------------------
__global__ void __launch_bounds__(256, 2)
vq_argmin_kernel(const float* __restrict__ z)
{
    extern __shared__ char smem[];
    unsigned long long* s_z  = (unsigned long long*)(smem + SM_Z);
    unsigned long long* s_e  = (unsigned long long*)(smem + SM_E);
    float*              s_s2 = (float*)(smem + SM_S2);
    float*              s_zf = (float*)(smem + SM_Z);

    const int tid = threadIdx.x;
    const int ry  = tid >> 3;     // 0..31  -> rows ry*4..ry*4+3
    const int cx  = tid & 7;      // 0..7   -> codes cx*8..cx*8+7 per tile
    const int r0  = blockIdx.x * 128;
    const int b   = r0 >> 12;
    const int hw0 = r0 & 4095;

    // stage s2 table
    #pragma unroll
    for (int i = 0; i < 4; i++) s_s2[tid + i * 256] = g_s2[tid + i * 256];

    // stage z tile as pairs [k2][row] (coalesced gmem float4 reads)
    const float* zb = z + (size_t)b * (DIM * HW) + hw0;
    #pragma unroll
    for (int i = 0; i < 8; i++) {
        int idx = tid + i * 256;         // 0..2047
        int k = idx >> 5;                // dim
        int g = idx & 31;                // group of 4 rows
        float4 v = *(const float4*)(zb + (size_t)k * HW + g * 4);
        int base = ((k >> 1) * 128 + g * 4) * 2 + (k & 1);
        s_zf[base]     = v.x;
        s_zf[base + 2] = v.y;
        s_zf[base + 4] = v.z;
        s_zf[base + 6] = v.w;
    }
    __syncthreads();

    // exact s1 per owned row: fp64 sum of fp32 squares, ascending k (proven)
    float s1[4];
    #pragma unroll
    for (int i = 0; i < 4; i++) {
        const int row = ry * 4 + i;
        double acc = 0.0;
        #pragma unroll
        for (int k2 = 0; k2 < 32; k2++) {
            float lo, hi; unpack2(s_z[k2 * 128 + row], lo, hi);
            acc += (double)__fmul_rn(lo, lo);
            acc += (double)__fmul_rn(hi, hi);
        }
        s1[i] = (float)acc;
    }

    unsigned long long acc[4][8];
    #pragma unroll
    for (int i = 0; i < 4; i++)
        #pragma unroll
        for (int j = 0; j < 8; j++) acc[i][j] = 0ull;

    float best[4];
    int   bidx[4];
    #pragma unroll
    for (int i = 0; i < 4; i++) { best[i] = CUDART_INF_F; bidx[i] = 0; }

    for (int tn = 0; tn < N_TILES; tn++) {
        // stage code tile (contiguous copy; layout precomputed in prep)
        const unsigned long long* src = g_cbt + tn * 2048;
        #pragma unroll
        for (int i = 0; i < 8; i++)
            s_e[tid + i * 256] = src[tid + i * 256];
        __syncthreads();

        #pragma unroll 4
        for (int k2 = 0; k2 < 32; k2++) {
            unsigned long long zr[4], er[8];
            #pragma unroll
            for (int m = 0; m < 2; m++) {
                ulonglong2 v = *(const ulonglong2*)&s_z[k2 * 128 + ry * 4 + 2 * m];
                zr[2 * m] = v.x; zr[2 * m + 1] = v.y;
            }
            #pragma unroll
            for (int m = 0; m < 4; m++) {
                ulonglong2 v = *(const ulonglong2*)&s_e[(k2 * 4 + m) * 16 + cx * 2];
                er[2 * m] = v.x; er[2 * m + 1] = v.y;
            }
            #pragma unroll
            for (int i = 0; i < 4; i++)
                #pragma unroll
                for (int j = 0; j < 8; j++)
                    fma2(acc[i][j], zr[i], er[j]);
        }

        // epilogue: fold + compare (codes ascending in j per thread)
        const int c0 = tn * 64 + cx * 8;
        float4 s2a = *(const float4*)&s_s2[c0];
        float4 s2b = *(const float4*)&s_s2[c0 + 4];
        float s2v[8] = {s2a.x, s2a.y, s2a.z, s2a.w, s2b.x, s2b.y, s2b.z, s2b.w};
        #pragma unroll
        for (int i = 0; i < 4; i++) {
            #pragma unroll
            for (int j = 0; j < 8; j++) {
                float lo, hi; unpack2(acc[i][j], lo, hi);
                float cross = __fadd_rn(lo, hi);
                float tt    = __fadd_rn(s1[i], s2v[j]);
                float score = __fmaf_rn(-2.0f, cross, tt);
                if (score < best[i]) { best[i] = score; bidx[i] = c0 + j; }
                acc[i][j] = 0ull;
            }
        }
        __syncthreads();   // reads done before next tile overwrites s_e
    }

    // merge across the 8 code lanes (same rows): min score, tie -> min index
    #pragma unroll
    for (int off = 1; off <= 4; off <<= 1) {
        #pragma unroll
        for (int i = 0; i < 4; i++) {
            float os = __shfl_down_sync(0xffffffffu, best[i], off);
            int   oi = __shfl_down_sync(0xffffffffu, bidx[i], off);
            if (os < best[i] || (os == best[i] && oi < bidx[i])) {
                best[i] = os; bidx[i] = oi;
            }
        }
    }
    if (cx == 0) {
        #pragma unroll
        for (int i = 0; i < 4; i++)
            g_best_idx[r0 + ry * 4 + i] = bidx[i];
    }
}

// ---------------------------------------------------------------------------
// Kernel 2: gather + straight-through output + fp64 partial sums (proven,
// measured 54 us)
// ---------------------------------------------------------------------------
__global__ void __launch_bounds__(K2_THREADS)
vq_apply_kernel(const float* __restrict__ z, const float* __restrict__ cb,
                float* __restrict__ out)
{
    __shared__ double s_warp[K2_THREADS / 32];

    const int tid  = threadIdx.x;
    const int lane = tid & 31;
    const int wid  = tid >> 5;
    const long long base = ((long long)blockIdx.x * K2_THREADS + tid) * 16;

    const int b   = (int)(base >> 18);
    const int cch = (int)(base >> 12) & 63;
    const int h   = (int)(base >> 6) & 63;
    const int w   = (int)base & 63;
    const int row0 = b * HW + h * 64 + w;

    double acc = 0.0;
    #pragma unroll
    for (int g = 0; g < 4; g++) {
        float4 zv = *(const float4*)(z + base + 4 * g);
        int4   iv = *(const int4*)(g_best_idx + row0 + 4 * g);

        float q0 = cb[iv.x * DIM + cch];
        float q1 = cb[iv.y * DIM + cch];
        float q2 = cb[iv.z * DIM + cch];
        float q3 = cb[iv.w * DIM + cch];

        float d0 = __fadd_rn(q0, -zv.x);
        float d1 = __fadd_rn(q1, -zv.y);
        float d2 = __fadd_rn(q2, -zv.z);
        float d3 = __fadd_rn(q3, -zv.w);

        float4 ov;
        ov.x = __fadd_rn(zv.x, d0);
        ov.y = __fadd_rn(zv.y, d1);
        ov.z = __fadd_rn(zv.z, d2);
        ov.w = __fadd_rn(zv.w, d3);
        *(float4*)(out + base + 4 * g) = ov;

        float sg = __fadd_rn(__fadd_rn(__fmul_rn(d0, d0), __fmul_rn(d1, d1)),
                             __fadd_rn(__fmul_rn(d2, d2), __fmul_rn(d3, d3)));
        acc += (double)sg;
    }

    #pragma unroll
    for (int off = 16; off > 0; off >>= 1)
        acc += __shfl_down_sync(0xffffffffu, acc, off);
    if (lane == 0) s_warp[wid] = acc;
    __syncthreads();
    if (wid == 0) {
        double v = s_warp[lane];
        #pragma unroll
        for (int off = 16; off > 0; off >>= 1)
            v += __shfl_down_sync(0xffffffffu, v, off);
        if (lane == 0) g_partials[blockIdx.x] = v;
    }
}

// ---------------------------------------------------------------------------
// Kernel 3: deterministic final reduction + loss
// ---------------------------------------------------------------------------
__global__ void __launch_bounds__(K2_BLOCKS)
vq_loss_kernel(float* __restrict__ out, long long loss_pos)
{
    __shared__ double s_buf[K2_BLOCKS];
    const int tid = threadIdx.x;
    s_buf[tid] = g_partials[tid];
    __syncthreads();
    #pragma unroll
    for (int s = K2_BLOCKS / 2; s > 0; s >>= 1) {
        if (tid < s) s_buf[tid] += s_buf[tid + s];
        __syncthreads();
    }
    if (tid == 0) {
        float m = (float)(s_buf[0] * (1.0 / (double)N_ELEMS));
        float v = __fadd_rn(m, __fmul_rn(0.25f, m));
        out[loss_pos] = v;
    }
}

// ---------------------------------------------------------------------------
extern "C" void kernel_launch(void* const* d_in, const int* in_sizes, int n_in,
                              void* d_out, int out_size)
{
    const float* z  = (const float*)d_in[0];   // [32, 64, 64, 64] fp32
    const float* cb = (const float*)d_in[1];   // [1024, 64] fp32
    float* out = (float*)d_out;                // [8388608 z_q_st] + [1 loss]

    cudaFuncSetAttribute(vq_argmin_kernel,
                         cudaFuncAttributeMaxDynamicSharedMemorySize, SMEM_TOTAL);

    vq_prep_kernel<<<4, 256>>>(cb);
    vq_argmin_kernel<<<N_ROWS / 128, 256, SMEM_TOTAL>>>(z);
    vq_apply_kernel<<<K2_BLOCKS, K2_THREADS>>>(z, cb, out);

    long long loss_pos = (long long)out_size - 1;
    if (loss_pos < N_ELEMS) loss_pos = N_ELEMS;  // defensive; expect 8388609
    vq_loss_kernel<<<1, K2_BLOCKS>>>(out, loss_pos);
}

// round 16
// speedup vs baseline: 2.5372x; 1.2954x over previous
#include <cuda_runtime.h>
#include <math_constants.h>
#include <cstdint>

// Problem constants
#define NB      32
#define DIM     64
#define HW      4096            // 64*64
#define N_ROWS  (NB * HW)       // 131072
#define N_CODES 1024
#define N_ELEMS (N_ROWS * DIM)  // 8388608

#define N_TILES 16              // code tiles of 64
#define K2_BLOCKS  512
#define K2_THREADS 1024

// Dynamic smem layout for argmin kernel
#define SM_Z   0                // ulonglong [32][128] = 32768 B (z pairs [k2][row])
#define SM_E   32768            // ulonglong [32][64]  = 16384 B (code pairs [k2][c])
#define SM_S2  49152            // float [1024]        = 4096 B
#define SM_S1  53248            // float [128]         = 512 B
#define SMEM_TOTAL 53760

// Device scratch (no allocations allowed)
__device__ int                g_best_idx[N_ROWS];
__device__ double             g_partials[K2_BLOCKS];
__device__ float              g_s2[N_CODES];
__device__ unsigned long long g_cbt[N_CODES * 32];   // [tile][k2][c] packed pairs

// ---- packed fp32x2 helpers (sm_100+) ---------------------------------------
__device__ __forceinline__ void fma2(unsigned long long& d,
                                     unsigned long long a,
                                     unsigned long long b) {
    asm("fma.rn.f32x2 %0, %1, %2, %0;" : "+l"(d) : "l"(a), "l"(b));
}
__device__ __forceinline__ unsigned long long pack2(float lo, float hi) {
    unsigned long long r;
    asm("mov.b64 %0, {%1, %2};" : "=l"(r) : "f"(lo), "f"(hi));
    return r;
}
__device__ __forceinline__ void unpack2(unsigned long long p, float& lo, float& hi) {
    asm("mov.b64 {%0, %1}, %2;" : "=f"(lo), "=f"(hi) : "l"(p));
}

// ---------------------------------------------------------------------------
// Kernel 0 (prep): exact per-code s2 (sequential fp32 chain, proven) and the
// pair-transposed codebook g_cbt[tile*2048 + k2*64 + cloc] (R11 layout).
// ---------------------------------------------------------------------------
__global__ void __launch_bounds__(256)
vq_prep_kernel(const float* __restrict__ cb)
{
    const int c = blockIdx.x * 256 + threadIdx.x;
    if (c >= N_CODES) return;
    const float* ep = cb + (size_t)c * DIM;
    const int tbase = (c >> 6) * 2048 + (c & 63);
    float acc = 0.0f;
    #pragma unroll
    for (int k2 = 0; k2 < 32; k2++) {
        float e0 = ep[2 * k2];
        float e1 = ep[2 * k2 + 1];
        acc = __fadd_rn(acc, __fmul_rn(e0, e0));
        acc = __fadd_rn(acc, __fmul_rn(e1, e1));
        g_cbt[tbase + k2 * 64] = pack2(e0, e1);
    }
    g_s2[c] = acc;
}

// ---------------------------------------------------------------------------
// Kernel 1: register-tiled argmin (R11 hot loop, byte-equivalent; proven
// 527 us total / rel_err 0.0). Single change: s1 is computed ONCE per row
// (threads tid<128) instead of 8x redundantly per thread, removing ~7/8 of
// the fp64 preamble work. Score chain identical to the seven passing rounds.
// ---------------------------------------------------------------------------
__global__ void __launch_bounds__(256, 2)
vq_argmin_kernel(const float* __restrict__ z)
{
    extern __shared__ char smem[];
    unsigned long long* s_z  = (unsigned long long*)(smem + SM_Z);
    unsigned long long* s_e  = (unsigned long long*)(smem + SM_E);
    float*              s_s2 = (float*)(smem + SM_S2);
    float*              s_s1 = (float*)(smem + SM_S1);
    float*              s_zf = (float*)(smem + SM_Z);

    const int tid = threadIdx.x;
    const int ry  = tid >> 3;     // 0..31  -> rows ry*4..ry*4+3
    const int cx  = tid & 7;      // 0..7   -> code lane
    const int r0  = blockIdx.x * 128;
    const int b   = r0 >> 12;
    const int hw0 = r0 & 4095;

    // stage s2 table
    #pragma unroll
    for (int i = 0; i < 4; i++) s_s2[tid + i * 256] = g_s2[tid + i * 256];

    // stage z tile as pairs [k2][row] (coalesced gmem float4 reads)
    const float* zb = z + (size_t)b * (DIM * HW) + hw0;
    #pragma unroll
    for (int i = 0; i < 8; i++) {
        int idx = tid + i * 256;         // 0..2047
        int k = idx >> 5;                // dim
        int g = idx & 31;                // group of 4 rows
        float4 v = *(const float4*)(zb + (size_t)k * HW + g * 4);
        int base = ((k >> 1) * 128 + g * 4) * 2 + (k & 1);
        s_zf[base]     = v.x;
        s_zf[base + 2] = v.y;
        s_zf[base + 4] = v.z;
        s_zf[base + 6] = v.w;
    }
    __syncthreads();

    // s1 once per row: fp64 sum of fp32 squares, ascending k. fp64 error is
    // ~2^-52 vs fp32 ulp 2^-23, so the fp32 cast is correctly rounded and
    // identical to the proven per-thread version.
    if (tid < 128) {
        double acc = 0.0;
        #pragma unroll
        for (int k2 = 0; k2 < 32; k2++) {
            float lo, hi; unpack2(s_z[k2 * 128 + tid], lo, hi);
            acc += (double)__fmul_rn(lo, lo);
            acc += (double)__fmul_rn(hi, hi);
        }
        s_s1[tid] = (float)acc;
    }
    __syncthreads();

    float s1[4];
    #pragma unroll
    for (int i = 0; i < 4; i++) s1[i] = s_s1[ry * 4 + i];

    unsigned long long acc[4][8];
    #pragma unroll
    for (int i = 0; i < 4; i++)
        #pragma unroll
        for (int j = 0; j < 8; j++) acc[i][j] = 0ull;

    float best[4];
    int   bidx[4];
    #pragma unroll
    for (int i = 0; i < 4; i++) { best[i] = CUDART_INF_F; bidx[i] = 0; }

    for (int tn = 0; tn < N_TILES; tn++) {
        // stage code tile [k2][c] (contiguous, coalesced)
        const unsigned long long* src = g_cbt + tn * 2048;
        #pragma unroll
        for (int i = 0; i < 8; i++)
            s_e[tid + i * 256] = src[tid + i * 256];
        __syncthreads();

        #pragma unroll 8
        for (int k2 = 0; k2 < 32; k2++) {
            unsigned long long zr[4], er[8];
            #pragma unroll
            for (int i = 0; i < 4; i++) zr[i] = s_z[k2 * 128 + ry * 4 + i];
            #pragma unroll
            for (int j = 0; j < 8; j++) er[j] = s_e[k2 * 64 + cx + 8 * j];
            #pragma unroll
            for (int i = 0; i < 4; i++)
                #pragma unroll
                for (int j = 0; j < 8; j++)
                    fma2(acc[i][j], zr[i], er[j]);
        }

        // epilogue: fold + compare (codes ascending in j per thread)
        const int c0 = tn * 64 + cx;
        #pragma unroll
        for (int i = 0; i < 4; i++) {
            #pragma unroll
            for (int j = 0; j < 8; j++) {
                float lo, hi; unpack2(acc[i][j], lo, hi);
                float cross = __fadd_rn(lo, hi);
                const int code = c0 + 8 * j;
                float tt    = __fadd_rn(s1[i], s_s2[code]);
                float score = __fmaf_rn(-2.0f, cross, tt);
                if (score < best[i]) { best[i] = score; bidx[i] = code; }
                acc[i][j] = 0ull;
            }
        }
        __syncthreads();   // reads done before next tile overwrites s_e
    }

    // merge across the 8 code lanes (same rows): min score, tie -> min index
    #pragma unroll
    for (int off = 1; off <= 4; off <<= 1) {
        #pragma unroll
        for (int i = 0; i < 4; i++) {
            float os = __shfl_down_sync(0xffffffffu, best[i], off);
            int   oi = __shfl_down_sync(0xffffffffu, bidx[i], off);
            if (os < best[i] || (os == best[i] && oi < bidx[i])) {
                best[i] = os; bidx[i] = oi;
            }
        }
    }
    if (cx == 0) {
        #pragma unroll
        for (int i = 0; i < 4; i++)
            g_best_idx[r0 + ry * 4 + i] = bidx[i];
    }
}

// ---------------------------------------------------------------------------
// Kernel 2: gather + straight-through output + fp64 partial sums (proven)
// ---------------------------------------------------------------------------
__global__ void __launch_bounds__(K2_THREADS)
vq_apply_kernel(const float* __restrict__ z, const float* __restrict__ cb,
                float* __restrict__ out)
{
    __shared__ double s_warp[K2_THREADS / 32];

    const int tid  = threadIdx.x;
    const int lane = tid & 31;
    const int wid  = tid >> 5;
    const long long base = ((long long)blockIdx.x * K2_THREADS + tid) * 16;

    const int b   = (int)(base >> 18);
    const int cch = (int)(base >> 12) & 63;
    const int h   = (int)(base >> 6) & 63;
    const int w   = (int)base & 63;
    const int row0 = b * HW + h * 64 + w;

    double acc = 0.0;
    #pragma unroll
    for (int g = 0; g < 4; g++) {
        float4 zv = *(const float4*)(z + base + 4 * g);
        int4   iv = *(const int4*)(g_best_idx + row0 + 4 * g);

        float q0 = cb[iv.x * DIM + cch];
        float q1 = cb[iv.y * DIM + cch];
        float q2 = cb[iv.z * DIM + cch];
        float q3 = cb[iv.w * DIM + cch];

        float d0 = __fadd_rn(q0, -zv.x);
        float d1 = __fadd_rn(q1, -zv.y);
        float d2 = __fadd_rn(q2, -zv.z);
        float d3 = __fadd_rn(q3, -zv.w);

        float4 ov;
        ov.x = __fadd_rn(zv.x, d0);
        ov.y = __fadd_rn(zv.y, d1);
        ov.z = __fadd_rn(zv.z, d2);
        ov.w = __fadd_rn(zv.w, d3);
        *(float4*)(out + base + 4 * g) = ov;

        float sg = __fadd_rn(__fadd_rn(__fmul_rn(d0, d0), __fmul_rn(d1, d1)),
                             __fadd_rn(__fmul_rn(d2, d2), __fmul_rn(d3, d3)));
        acc += (double)sg;
    }

    #pragma unroll
    for (int off = 16; off > 0; off >>= 1)
        acc += __shfl_down_sync(0xffffffffu, acc, off);
    if (lane == 0) s_warp[wid] = acc;
    __syncthreads();
    if (wid == 0) {
        double v = s_warp[lane];
        #pragma unroll
        for (int off = 16; off > 0; off >>= 1)
            v += __shfl_down_sync(0xffffffffu, v, off);
        if (lane == 0) g_partials[blockIdx.x] = v;
    }
}

// ---------------------------------------------------------------------------
// Kernel 3: deterministic final reduction + loss
// ---------------------------------------------------------------------------
__global__ void __launch_bounds__(K2_BLOCKS)
vq_loss_kernel(float* __restrict__ out, long long loss_pos)
{
    __shared__ double s_buf[K2_BLOCKS];
    const int tid = threadIdx.x;
    s_buf[tid] = g_partials[tid];
    __syncthreads();
    #pragma unroll
    for (int s = K2_BLOCKS / 2; s > 0; s >>= 1) {
        if (tid < s) s_buf[tid] += s_buf[tid + s];
        __syncthreads();
    }
    if (tid == 0) {
        float m = (float)(s_buf[0] * (1.0 / (double)N_ELEMS));
        float v = __fadd_rn(m, __fmul_rn(0.25f, m));
        out[loss_pos] = v;
    }
}

// ---------------------------------------------------------------------------
extern "C" void kernel_launch(void* const* d_in, const int* in_sizes, int n_in,
                              void* d_out, int out_size)
{
    const float* z  = (const float*)d_in[0];   // [32, 64, 64, 64] fp32
    const float* cb = (const float*)d_in[1];   // [1024, 64] fp32
    float* out = (float*)d_out;                // [8388608 z_q_st] + [1 loss]

    cudaFuncSetAttribute(vq_argmin_kernel,
                         cudaFuncAttributeMaxDynamicSharedMemorySize, SMEM_TOTAL);

    vq_prep_kernel<<<4, 256>>>(cb);
    vq_argmin_kernel<<<N_ROWS / 128, 256, SMEM_TOTAL>>>(z);
    vq_apply_kernel<<<K2_BLOCKS, K2_THREADS>>>(z, cb, out);

    long long loss_pos = (long long)out_size - 1;
    if (loss_pos < N_ELEMS) loss_pos = N_ELEMS;  // defensive; expect 8388609
    vq_loss_kernel<<<1, K2_BLOCKS>>>(out, loss_pos);
}

// round 17
// speedup vs baseline: 2.5598x; 1.0089x over previous
#include <cuda_runtime.h>
#include <math_constants.h>
#include <cstdint>

// Problem constants
#define NB      32
#define DIM     64
#define HW      4096            // 64*64
#define N_ROWS  (NB * HW)       // 131072
#define N_CODES 1024
#define N_ELEMS (N_ROWS * DIM)  // 8388608

#define N_TILES 16              // code tiles of 64
#define A_BLOCKS 1024           // apply blocks (128 rows each)

// Dynamic smem layout for argmin kernel
#define SM_Z   0                // ulonglong [32][128] = 32768 B (z pairs [k2][row])
#define SM_E   32768            // ulonglong [32][64]  = 16384 B (code pairs [k2][c])
#define SM_S2  49152            // float [1024]        = 4096 B
#define SM_S1  53248            // float [128]         = 512 B
#define SMEM_TOTAL 53760

// Device scratch (no allocations allowed)
__device__ int                g_best_idx[N_ROWS];
__device__ double             g_partials[A_BLOCKS];
__device__ float              g_s2[N_CODES];
__device__ unsigned long long g_cbt[N_CODES * 32];   // [tile][k2][c] packed pairs

// ---- packed fp32x2 helpers (sm_100+) ---------------------------------------
__device__ __forceinline__ void fma2(unsigned long long& d,
                                     unsigned long long a,
                                     unsigned long long b) {
    asm("fma.rn.f32x2 %0, %1, %2, %0;" : "+l"(d) : "l"(a), "l"(b));
}
__device__ __forceinline__ unsigned long long pack2(float lo, float hi) {
    unsigned long long r;
    asm("mov.b64 %0, {%1, %2};" : "=l"(r) : "f"(lo), "f"(hi));
    return r;
}
__device__ __forceinline__ void unpack2(unsigned long long p, float& lo, float& hi) {
    asm("mov.b64 {%0, %1}, %2;" : "=f"(lo), "=f"(hi) : "l"(p));
}

// ---------------------------------------------------------------------------
// Kernel 0 (prep): exact per-code s2 (sequential fp32 chain, proven) and the
// pair-transposed codebook g_cbt[tile*2048 + k2*64 + cloc] (R11 layout).
// ---------------------------------------------------------------------------
__global__ void __launch_bounds__(256)
vq_prep_kernel(const float* __restrict__ cb)
{
    const int c = blockIdx.x * 256 + threadIdx.x;
    if (c >= N_CODES) return;
    const float* ep = cb + (size_t)c * DIM;
    const int tbase = (c >> 6) * 2048 + (c & 63);
    float acc = 0.0f;
    #pragma unroll
    for (int k2 = 0; k2 < 32; k2++) {
        float e0 = ep[2 * k2];
        float e1 = ep[2 * k2 + 1];
        acc = __fadd_rn(acc, __fmul_rn(e0, e0));
        acc = __fadd_rn(acc, __fmul_rn(e1, e1));
        g_cbt[tbase + k2 * 64] = pack2(e0, e1);
    }
    g_s2[c] = acc;
}

// ---------------------------------------------------------------------------
// Kernel 1: register-tiled argmin — VERBATIM from R16 (446 us, rel_err 0.0).
// At the FFMA2 RF-banking floor (rt=3); do not touch.
// ---------------------------------------------------------------------------
__global__ void __launch_bounds__(256, 2)
vq_argmin_kernel(const float* __restrict__ z)
{
    extern __shared__ char smem[];
    unsigned long long* s_z  = (unsigned long long*)(smem + SM_Z);
    unsigned long long* s_e  = (unsigned long long*)(smem + SM_E);
    float*              s_s2 = (float*)(smem + SM_S2);
    float*              s_s1 = (float*)(smem + SM_S1);
    float*              s_zf = (float*)(smem + SM_Z);

    const int tid = threadIdx.x;
    const int ry  = tid >> 3;     // 0..31  -> rows ry*4..ry*4+3
    const int cx  = tid & 7;      // 0..7   -> code lane
    const int r0  = blockIdx.x * 128;
    const int b   = r0 >> 12;
    const int hw0 = r0 & 4095;

    // stage s2 table
    #pragma unroll
    for (int i = 0; i < 4; i++) s_s2[tid + i * 256] = g_s2[tid + i * 256];

    // stage z tile as pairs [k2][row] (coalesced gmem float4 reads)
    const float* zb = z + (size_t)b * (DIM * HW) + hw0;
    #pragma unroll
    for (int i = 0; i < 8; i++) {
        int idx = tid + i * 256;         // 0..2047
        int k = idx >> 5;                // dim
        int g = idx & 31;                // group of 4 rows
        float4 v = *(const float4*)(zb + (size_t)k * HW + g * 4);
        int base = ((k >> 1) * 128 + g * 4) * 2 + (k & 1);
        s_zf[base]     = v.x;
        s_zf[base + 2] = v.y;
        s_zf[base + 4] = v.z;
        s_zf[base + 6] = v.w;
    }
    __syncthreads();

    // s1 once per row: fp64 sum of fp32 squares, ascending k (proven)
    if (tid < 128) {
        double acc = 0.0;
        #pragma unroll
        for (int k2 = 0; k2 < 32; k2++) {
            float lo, hi; unpack2(s_z[k2 * 128 + tid], lo, hi);
            acc += (double)__fmul_rn(lo, lo);
            acc += (double)__fmul_rn(hi, hi);
        }
        s_s1[tid] = (float)acc;
    }
    __syncthreads();

    float s1[4];
    #pragma unroll
    for (int i = 0; i < 4; i++) s1[i] = s_s1[ry * 4 + i];

    unsigned long long acc[4][8];
    #pragma unroll
    for (int i = 0; i < 4; i++)
        #pragma unroll
        for (int j = 0; j < 8; j++) acc[i][j] = 0ull;

    float best[4];
    int   bidx[4];
    #pragma unroll
    for (int i = 0; i < 4; i++) { best[i] = CUDART_INF_F; bidx[i] = 0; }

    for (int tn = 0; tn < N_TILES; tn++) {
        const unsigned long long* src = g_cbt + tn * 2048;
        #pragma unroll
        for (int i = 0; i < 8; i++)
            s_e[tid + i * 256] = src[tid + i * 256];
        __syncthreads();

        #pragma unroll 8
        for (int k2 = 0; k2 < 32; k2++) {
            unsigned long long zr[4], er[8];
            #pragma unroll
            for (int i = 0; i < 4; i++) zr[i] = s_z[k2 * 128 + ry * 4 + i];
            #pragma unroll
            for (int j = 0; j < 8; j++) er[j] = s_e[k2 * 64 + cx + 8 * j];
            #pragma unroll
            for (int i = 0; i < 4; i++)
                #pragma unroll
                for (int j = 0; j < 8; j++)
                    fma2(acc[i][j], zr[i], er[j]);
        }

        const int c0 = tn * 64 + cx;
        #pragma unroll
        for (int i = 0; i < 4; i++) {
            #pragma unroll
            for (int j = 0; j < 8; j++) {
                float lo, hi; unpack2(acc[i][j], lo, hi);
                float cross = __fadd_rn(lo, hi);
                const int code = c0 + 8 * j;
                float tt    = __fadd_rn(s1[i], s_s2[code]);
                float score = __fmaf_rn(-2.0f, cross, tt);
                if (score < best[i]) { best[i] = score; bidx[i] = code; }
                acc[i][j] = 0ull;
            }
        }
        __syncthreads();
    }

    #pragma unroll
    for (int off = 1; off <= 4; off <<= 1) {
        #pragma unroll
        for (int i = 0; i < 4; i++) {
            float os = __shfl_down_sync(0xffffffffu, best[i], off);
            int   oi = __shfl_down_sync(0xffffffffu, bidx[i], off);
            if (os < best[i] || (os == best[i] && oi < bidx[i])) {
                best[i] = os; bidx[i] = oi;
            }
        }
    }
    if (cx == 0) {
        #pragma unroll
        for (int i = 0; i < 4; i++)
            g_best_idx[r0 + ry * 4 + i] = bidx[i];
    }
}

// ---------------------------------------------------------------------------
// Kernel 2: apply v2 — smem-staged gather. Block = 128 rows (<=128 distinct
// codes); stage those code rows coalesced into padded smem, then all gathers
// hit smem conflict-free. Element chain identical ops to the proven apply:
// d = RN(q - z); out = RN(z + d); dd += (double)RN(d*d).
// ---------------------------------------------------------------------------
__global__ void __launch_bounds__(256)
vq_apply_kernel(const float* __restrict__ z, const float* __restrict__ cb,
                float* __restrict__ out)
{
    __shared__ float  s_q[128 * 65];   // padded pitch 65 -> conflict-free gather
    __shared__ int    s_idx[128];
    __shared__ double s_rd[8];

    const int tid = threadIdx.x;
    const int r0  = blockIdx.x * 128;
    const int b   = r0 >> 12;
    const int hw0 = r0 & 4095;

    if (tid < 128) s_idx[tid] = g_best_idx[r0 + tid];
    __syncthreads();

    // stage the 128 selected code rows (16-B coalesced reads per row)
    const float4* cb4 = (const float4*)cb;
    #pragma unroll
    for (int it = 0; it < 8; it++) {
        int t = tid + it * 256;       // 0..2047
        int i = t >> 4;               // local row
        int g = t & 15;               // float4 chunk within code row
        float4 v = cb4[s_idx[i] * 16 + g];
        float* dst = &s_q[i * 65 + g * 4];
        dst[0] = v.x; dst[1] = v.y; dst[2] = v.z; dst[3] = v.w;
    }
    __syncthreads();

    const float* zb = z   + (size_t)b * (DIM * HW) + hw0;
    float*       ob = out + (size_t)b * (DIM * HW) + hw0;
    double dd = 0.0;
    #pragma unroll
    for (int it = 0; it < 32; it++) {
        const int idx = tid + it * 256;   // 0..8191
        const int c   = idx >> 7;         // channel 0..63
        const int i   = idx & 127;        // local row
        const float zv = zb[(size_t)c * HW + i];
        const float q  = s_q[i * 65 + c];
        const float d  = __fadd_rn(q, -zv);
        ob[(size_t)c * HW + i] = __fadd_rn(zv, d);
        dd += (double)__fmul_rn(d, d);
    }

    // deterministic block reduction
    const int lane = tid & 31;
    const int wid  = tid >> 5;
    #pragma unroll
    for (int off = 16; off > 0; off >>= 1)
        dd += __shfl_down_sync(0xffffffffu, dd, off);
    if (lane == 0) s_rd[wid] = dd;
    __syncthreads();
    if (tid == 0) {
        double v = 0.0;
        #pragma unroll
        for (int i = 0; i < 8; i++) v += s_rd[i];
        g_partials[blockIdx.x] = v;
    }
}

// ---------------------------------------------------------------------------
// Kernel 3: deterministic final reduction + loss
// ---------------------------------------------------------------------------
__global__ void __launch_bounds__(1024)
vq_loss_kernel(float* __restrict__ out, long long loss_pos)
{
    __shared__ double s_buf[A_BLOCKS];
    const int tid = threadIdx.x;
    s_buf[tid] = g_partials[tid];
    __syncthreads();
    #pragma unroll
    for (int s = A_BLOCKS / 2; s > 0; s >>= 1) {
        if (tid < s) s_buf[tid] += s_buf[tid + s];
        __syncthreads();
    }
    if (tid == 0) {
        float m = (float)(s_buf[0] * (1.0 / (double)N_ELEMS));
        float v = __fadd_rn(m, __fmul_rn(0.25f, m));
        out[loss_pos] = v;
    }
}

// ---------------------------------------------------------------------------
extern "C" void kernel_launch(void* const* d_in, const int* in_sizes, int n_in,
                              void* d_out, int out_size)
{
    const float* z  = (const float*)d_in[0];   // [32, 64, 64, 64] fp32
    const float* cb = (const float*)d_in[1];   // [1024, 64] fp32
    float* out = (float*)d_out;                // [8388608 z_q_st] + [1 loss]

    cudaFuncSetAttribute(vq_argmin_kernel,
                         cudaFuncAttributeMaxDynamicSharedMemorySize, SMEM_TOTAL);

    vq_prep_kernel<<<4, 256>>>(cb);
    vq_argmin_kernel<<<N_ROWS / 128, 256, SMEM_TOTAL>>>(z);
    vq_apply_kernel<<<A_BLOCKS, 256>>>(z, cb, out);

    long long loss_pos = (long long)out_size - 1;
    if (loss_pos < N_ELEMS) loss_pos = N_ELEMS;  // defensive; expect 8388609
    vq_loss_kernel<<<1, 1024>>>(out, loss_pos);
}